// round 5
// baseline (speedup 1.0000x reference)
#include <cuda_runtime.h>

#define Bd 8
#define Td 512
#define Cd 512
#define NHd 8
#define HDd 64
#define Md (Bd * Td)            // 4096
#define QKVN (3 * Cd)           // 1536

__device__ float g_qkv[Md * QKVN];
__device__ float g_y[Md * Cd];

__device__ __forceinline__ unsigned f2tf(float f) {
    unsigned u; asm("cvt.rna.tf32.f32 %0, %1;" : "=r"(u) : "f"(f)); return u;
}
__device__ __forceinline__ uint4 cvt4(float4 v) {
    return make_uint4(f2tf(v.x), f2tf(v.y), f2tf(v.z), f2tf(v.w));
}
__device__ __forceinline__ void mma_tf32(float c[4],
    unsigned a0, unsigned a1, unsigned a2, unsigned a3,
    unsigned b0, unsigned b1)
{
    asm volatile(
        "mma.sync.aligned.m16n8k8.row.col.f32.tf32.tf32.f32 "
        "{%0,%1,%2,%3}, {%4,%5,%6,%7}, {%8,%9}, {%0,%1,%2,%3};"
        : "+f"(c[0]), "+f"(c[1]), "+f"(c[2]), "+f"(c[3])
        : "r"(a0), "r"(a1), "r"(a2), "r"(a3), "r"(b0), "r"(b1));
}

// ---------------------------------------------------------------------------
// tf32 SGEMM: out[m,n] = A[m,:]·W[n,:] + bias[n]
// BM x 64 tile, BK=32, 256 threads, warps 4(M)x2(N).
// Register-prefetch pipeline: next k-block LDGs issued before compute.
// ---------------------------------------------------------------------------
#define GPITCH 36
template<int BM>
__global__ __launch_bounds__(256) void sgemm_bias_kernel(
    const float* __restrict__ A, const float* __restrict__ W,
    const float* __restrict__ bias, float* __restrict__ out,
    int Kdim, int Ndim)
{
    constexpr int MI = BM / 64;            // 16-row m-subtiles per warp
    constexpr int AL = BM / 32;            // float4 loads per thread for A
    __shared__ unsigned As[BM * GPITCH];
    __shared__ unsigned Bs[64 * GPITCH];
    const int tid = threadIdx.x;
    const int lane = tid & 31, warp = tid >> 5;
    const int g = lane >> 2, tig = lane & 3;
    const int wm = (warp & 3) * (BM / 4);
    const int wn = (warp >> 2) << 5;
    const int m0 = blockIdx.y * BM, n0 = blockIdx.x << 6;

    const int lrow = tid >> 3;             // 0..31
    const int lk4 = (tid & 7) << 2;        // 0,4,..,28

    float c[MI][4][4] = {};
    float4 avr[AL], bvr[2];

    // prime the pipeline
    #pragma unroll
    for (int i = 0; i < AL; i++)
        avr[i] = *(const float4*)&A[(size_t)(m0 + lrow + (i << 5)) * Kdim + lk4];
    #pragma unroll
    for (int i = 0; i < 2; i++)
        bvr[i] = *(const float4*)&W[(size_t)(n0 + lrow + (i << 5)) * Kdim + lk4];

    for (int k0 = 0; k0 < Kdim; k0 += 32) {
        #pragma unroll
        for (int i = 0; i < AL; i++)
            *(uint4*)&As[(lrow + (i << 5)) * GPITCH + lk4] = cvt4(avr[i]);
        #pragma unroll
        for (int i = 0; i < 2; i++)
            *(uint4*)&Bs[(lrow + (i << 5)) * GPITCH + lk4] = cvt4(bvr[i]);
        __syncthreads();

        if (k0 + 32 < Kdim) {               // prefetch next k-block
            #pragma unroll
            for (int i = 0; i < AL; i++)
                avr[i] = *(const float4*)&A[(size_t)(m0 + lrow + (i << 5)) * Kdim + k0 + 32 + lk4];
            #pragma unroll
            for (int i = 0; i < 2; i++)
                bvr[i] = *(const float4*)&W[(size_t)(n0 + lrow + (i << 5)) * Kdim + k0 + 32 + lk4];
        }

        #pragma unroll
        for (int ks = 0; ks < 4; ks++) {
            const int ko = ks << 3;
            unsigned a[MI][4];
            #pragma unroll
            for (int i = 0; i < MI; i++) {
                int mb = wm + (i << 4);
                a[i][0] = As[(mb + g) * GPITCH + ko + tig];
                a[i][1] = As[(mb + g + 8) * GPITCH + ko + tig];
                a[i][2] = As[(mb + g) * GPITCH + ko + tig + 4];
                a[i][3] = As[(mb + g + 8) * GPITCH + ko + tig + 4];
            }
            unsigned b[4][2];
            #pragma unroll
            for (int j = 0; j < 4; j++) {
                int nb = wn + (j << 3);
                b[j][0] = Bs[(nb + g) * GPITCH + ko + tig];
                b[j][1] = Bs[(nb + g) * GPITCH + ko + tig + 4];
            }
            #pragma unroll
            for (int i = 0; i < MI; i++)
                #pragma unroll
                for (int j = 0; j < 4; j++)
                    mma_tf32(c[i][j], a[i][0], a[i][1], a[i][2], a[i][3],
                             b[j][0], b[j][1]);
        }
        __syncthreads();
    }

    #pragma unroll
    for (int i = 0; i < MI; i++) {
        #pragma unroll
        for (int j = 0; j < 4; j++) {
            int row = m0 + wm + (i << 4) + g;
            int col = n0 + wn + (j << 3) + (tig << 1);
            float b0 = bias[col], b1 = bias[col + 1];
            *(float2*)&out[(size_t)row * Ndim + col] =
                make_float2(c[i][j][0] + b0, c[i][j][1] + b1);
            *(float2*)&out[(size_t)(row + 8) * Ndim + col] =
                make_float2(c[i][j][2] + b0, c[i][j][3] + b1);
        }
    }
}

// ---------------------------------------------------------------------------
// LayerNorm q,k segments in place. One block per (b,t) row.
// ---------------------------------------------------------------------------
__global__ __launch_bounds__(256) void ln_qk_kernel(
    float* __restrict__ qkv,
    const float* __restrict__ qg, const float* __restrict__ qb,
    const float* __restrict__ kg, const float* __restrict__ kb)
{
    const int bt = blockIdx.x;
    float* row = qkv + (size_t)bt * QKVN;
    const int tid = threadIdx.x;
    const int lane = tid & 31, w = tid >> 5;
    __shared__ float sh_s[8], sh_ss[8];

    #pragma unroll
    for (int seg = 0; seg < 2; seg++) {
        float* p = row + seg * Cd;
        const float* gam = seg ? kg : qg;
        const float* bet = seg ? kb : qb;
        float x0 = p[tid], x1 = p[tid + 256];
        float s = x0 + x1;
        float ss = x0 * x0 + x1 * x1;
        #pragma unroll
        for (int o = 16; o; o >>= 1) {
            s  += __shfl_xor_sync(0xffffffffu, s, o);
            ss += __shfl_xor_sync(0xffffffffu, ss, o);
        }
        if (lane == 0) { sh_s[w] = s; sh_ss[w] = ss; }
        __syncthreads();
        float tot = 0.f, tot2 = 0.f;
        #pragma unroll
        for (int i = 0; i < 8; i++) { tot += sh_s[i]; tot2 += sh_ss[i]; }
        float mu = tot * (1.0f / 512.0f);
        float var = tot2 * (1.0f / 512.0f) - mu * mu;
        float rstd = rsqrtf(var + 1e-5f);
        p[tid]       = (x0 - mu) * rstd * gam[tid]       + bet[tid];
        p[tid + 256] = (x1 - mu) * rstd * gam[tid + 256] + bet[tid + 256];
        __syncthreads();
    }
}

// ---------------------------------------------------------------------------
// Fused attention per (b, h, 64-row q block), tf32 mma, register-prefetched
// tile loads in every phase.
// ---------------------------------------------------------------------------
#define QP 68
#define SP 516
#define ATTN_SMEM ((2 * 64 * QP + 64 * SP) * 4)   // 166912 bytes

__global__ __launch_bounds__(256) void attn_kernel(
    const float* __restrict__ qkv,
    const float* __restrict__ rel_emb,
    float* __restrict__ yout)
{
    const int blk = blockIdx.x;
    const int qb = blk & 7;
    const int h  = (blk >> 3) & 7;
    const int b  = blk >> 6;
    const int q0 = qb << 6;
    const int ntiles = qb + 1;
    const int kmax = ntiles << 6;

    extern __shared__ float sm[];
    unsigned* q_s = (unsigned*)sm;                 // [64 q][QP]  tf32 bits
    unsigned* t_s = (unsigned*)(sm + 64 * QP);     // tile buffer (tf32 bits)
    float*    s_s = sm + 2 * 64 * QP;              // [64 q][SP]  scores fp32
    unsigned* s_u = (unsigned*)s_s;

    const int tid = threadIdx.x;
    const int lane = tid & 31, warp = tid >> 5;
    const int g = lane >> 2, tig = lane & 3;
    const int qm = (warp & 3) << 4;                // warp q rows (16)
    const int wn = (warp >> 2) << 5;               // warp n cols (32)

    const int lr = tid >> 4;                       // 0..15 row-group
    const int lc4 = (tid & 15) << 2;               // 0..60 col*4

    // ---- load q block (LN'd), row-major tf32 ----
    {
        const float* qbase = qkv + (size_t)(b * Td + q0) * QKVN + h * HDd;
        #pragma unroll
        for (int i = 0; i < 4; i++) {
            int r = lr + (i << 4);
            float4 v = *(const float4*)&qbase[(size_t)r * QKVN + lc4];
            *(uint4*)&q_s[r * QP + lc4] = cvt4(v);
        }
    }

    float4 pv[4];
    // prime Phase A prefetch
    {
        const float* kb0 = qkv + (size_t)(b * Td) * QKVN + Cd + h * HDd;
        #pragma unroll
        for (int i = 0; i < 4; i++)
            pv[i] = *(const float4*)&kb0[(size_t)(lr + (i << 4)) * QKVN + lc4];
    }
    __syncthreads();

    // ---- Phase A: S = q @ k^T over causal key tiles ----
    for (int kt = 0; kt < ntiles; kt++) {
        #pragma unroll
        for (int i = 0; i < 4; i++)
            *(uint4*)&t_s[(lr + (i << 4)) * QP + lc4] = cvt4(pv[i]);
        __syncthreads();
        if (kt + 1 < ntiles) {
            const float* kbn = qkv + (size_t)(b * Td + ((kt + 1) << 6)) * QKVN + Cd + h * HDd;
            #pragma unroll
            for (int i = 0; i < 4; i++)
                pv[i] = *(const float4*)&kbn[(size_t)(lr + (i << 4)) * QKVN + lc4];
        } else {
            const float* rb0 = rel_emb + h * HDd;   // first Phase-B tile
            #pragma unroll
            for (int i = 0; i < 4; i++)
                pv[i] = *(const float4*)&rb0[(size_t)(lr + (i << 4)) * Cd + lc4];
        }
        float c[4][4] = {};
        #pragma unroll
        for (int ks = 0; ks < 8; ks++) {
            const int ko = ks << 3;
            unsigned a0 = q_s[(qm + g) * QP + ko + tig];
            unsigned a1 = q_s[(qm + g + 8) * QP + ko + tig];
            unsigned a2 = q_s[(qm + g) * QP + ko + tig + 4];
            unsigned a3 = q_s[(qm + g + 8) * QP + ko + tig + 4];
            #pragma unroll
            for (int j = 0; j < 4; j++) {
                unsigned b0 = t_s[(wn + (j << 3) + g) * QP + ko + tig];
                unsigned b1 = t_s[(wn + (j << 3) + g) * QP + ko + tig + 4];
                mma_tf32(c[j], a0, a1, a2, a3, b0, b1);
            }
        }
        #pragma unroll
        for (int j = 0; j < 4; j++) {
            int col = (kt << 6) + wn + (j << 3) + (tig << 1);
            *(float2*)&s_s[(qm + g) * SP + col]     = make_float2(c[j][0], c[j][1]);
            *(float2*)&s_s[(qm + g + 8) * SP + col] = make_float2(c[j][2], c[j][3]);
        }
        __syncthreads();
    }

    // ---- Phase B: P = q @ rel_h^T, scatter-add P[q, q-k] into scores ----
    for (int dt = 0; dt < ntiles; dt++) {
        #pragma unroll
        for (int i = 0; i < 4; i++)
            *(uint4*)&t_s[(lr + (i << 4)) * QP + lc4] = cvt4(pv[i]);
        __syncthreads();
        if (dt + 1 < ntiles) {
            const float* rbn = rel_emb + (size_t)((dt + 1) << 6) * Cd + h * HDd;
            #pragma unroll
            for (int i = 0; i < 4; i++)
                pv[i] = *(const float4*)&rbn[(size_t)(lr + (i << 4)) * Cd + lc4];
        } else {
            const float* vb0 = qkv + (size_t)(b * Td) * QKVN + 2 * Cd + h * HDd;
            #pragma unroll
            for (int i = 0; i < 4; i++)
                pv[i] = *(const float4*)&vb0[(size_t)(lr + (i << 4)) * QKVN + lc4];
        }
        float c[4][4] = {};
        #pragma unroll
        for (int ks = 0; ks < 8; ks++) {
            const int ko = ks << 3;
            unsigned a0 = q_s[(qm + g) * QP + ko + tig];
            unsigned a1 = q_s[(qm + g + 8) * QP + ko + tig];
            unsigned a2 = q_s[(qm + g) * QP + ko + tig + 4];
            unsigned a3 = q_s[(qm + g + 8) * QP + ko + tig + 4];
            #pragma unroll
            for (int j = 0; j < 4; j++) {
                unsigned b0 = t_s[(wn + (j << 3) + g) * QP + ko + tig];
                unsigned b1 = t_s[(wn + (j << 3) + g) * QP + ko + tig + 4];
                mma_tf32(c[j], a0, a1, a2, a3, b0, b1);
            }
        }
        #pragma unroll
        for (int j = 0; j < 4; j++) {
            int dglob = (dt << 6) + wn + (j << 3) + (tig << 1);
            int r0 = qm + g, r1 = qm + g + 8;
            int ki0 = (q0 + r0) - dglob;
            int ki1 = (q0 + r1) - dglob;
            if (ki0 >= 0)     s_s[r0 * SP + ki0]     += c[j][0];
            if (ki0 - 1 >= 0) s_s[r0 * SP + ki0 - 1] += c[j][1];
            if (ki1 >= 0)     s_s[r1 * SP + ki1]     += c[j][2];
            if (ki1 - 1 >= 0) s_s[r1 * SP + ki1 - 1] += c[j][3];
        }
        __syncthreads();
    }

    // ---- Phase C: causal softmax; write probabilities back as tf32 bits ----
    const float scale = 0.125f;
    for (int r = warp << 3; r < (warp << 3) + 8; r++) {
        const int qg_ = q0 + r;
        float mx = -1e30f;
        for (int col = lane; col < kmax; col += 32)
            if (col <= qg_) mx = fmaxf(mx, s_s[r * SP + col]);
        #pragma unroll
        for (int o = 16; o; o >>= 1)
            mx = fmaxf(mx, __shfl_xor_sync(0xffffffffu, mx, o));
        mx *= scale;
        float sum = 0.f;
        for (int col = lane; col < kmax; col += 32) {
            float v = 0.f;
            if (col <= qg_) {
                v = __expf(s_s[r * SP + col] * scale - mx);
                sum += v;
            }
            s_s[r * SP + col] = v;
        }
        #pragma unroll
        for (int o = 16; o; o >>= 1)
            sum += __shfl_xor_sync(0xffffffffu, sum, o);
        float inv = 1.0f / sum;
        for (int col = lane; col < kmax; col += 32)
            s_u[r * SP + col] = f2tf(s_s[r * SP + col] * inv);
    }
    __syncthreads();

    // ---- Phase D: O = P @ V (V tile stored transposed [d][key]) ----
    float o[4][4] = {};
    for (int kt = 0; kt < ntiles; kt++) {
        #pragma unroll
        for (int i = 0; i < 4; i++) {
            int key = lr + (i << 4);
            t_s[(lc4 + 0) * QP + key] = f2tf(pv[i].x);
            t_s[(lc4 + 1) * QP + key] = f2tf(pv[i].y);
            t_s[(lc4 + 2) * QP + key] = f2tf(pv[i].z);
            t_s[(lc4 + 3) * QP + key] = f2tf(pv[i].w);
        }
        __syncthreads();
        if (kt + 1 < ntiles) {
            const float* vbn = qkv + (size_t)(b * Td + ((kt + 1) << 6)) * QKVN + 2 * Cd + h * HDd;
            #pragma unroll
            for (int i = 0; i < 4; i++)
                pv[i] = *(const float4*)&vbn[(size_t)(lr + (i << 4)) * QKVN + lc4];
        }
        #pragma unroll
        for (int ks = 0; ks < 8; ks++) {
            const int ko = (kt << 6) + (ks << 3);   // column in s_u
            const int kl = ks << 3;                 // key within tile
            unsigned a0 = s_u[(qm + g) * SP + ko + tig];
            unsigned a1 = s_u[(qm + g + 8) * SP + ko + tig];
            unsigned a2 = s_u[(qm + g) * SP + ko + tig + 4];
            unsigned a3 = s_u[(qm + g + 8) * SP + ko + tig + 4];
            #pragma unroll
            for (int j = 0; j < 4; j++) {
                unsigned b0 = t_s[(wn + (j << 3) + g) * QP + kl + tig];
                unsigned b1 = t_s[(wn + (j << 3) + g) * QP + kl + tig + 4];
                mma_tf32(o[j], a0, a1, a2, a3, b0, b1);
            }
        }
        __syncthreads();
    }
    #pragma unroll
    for (int j = 0; j < 4; j++) {
        int row = q0 + qm + g;
        int col = h * HDd + wn + (j << 3) + (tig << 1);
        *(float2*)&yout[(size_t)(b * Td + row) * Cd + col] =
            make_float2(o[j][0], o[j][1]);
        *(float2*)&yout[(size_t)(b * Td + row + 8) * Cd + col] =
            make_float2(o[j][2], o[j][3]);
    }
}

// ---------------------------------------------------------------------------
extern "C" void kernel_launch(void* const* d_in, const int* in_sizes, int n_in,
                              void* d_out, int out_size)
{
    const float* x      = (const float*)d_in[0];
    const float* w_attn = (const float*)d_in[1];
    const float* b_attn = (const float*)d_in[2];
    const float* w_proj = (const float*)d_in[3];
    const float* b_proj = (const float*)d_in[4];
    const float* qg     = (const float*)d_in[5];
    const float* qbeta  = (const float*)d_in[6];
    const float* kg     = (const float*)d_in[7];
    const float* kbeta  = (const float*)d_in[8];
    const float* rel    = (const float*)d_in[9];
    float* out = (float*)d_out;

    float *qkv_p, *y_p;
    cudaGetSymbolAddress((void**)&qkv_p, g_qkv);
    cudaGetSymbolAddress((void**)&y_p, g_y);

    cudaFuncSetAttribute(attn_kernel,
                         cudaFuncAttributeMaxDynamicSharedMemorySize, ATTN_SMEM);

    // 1) QKV projection  (BM=128 -> 768 CTAs)
    {
        dim3 grid(QKVN / 64, Md / 128);
        sgemm_bias_kernel<128><<<grid, 256>>>(x, w_attn, b_attn, qkv_p, Cd, QKVN);
    }
    // 2) LayerNorm q,k in place
    ln_qk_kernel<<<Md, 256>>>(qkv_p, qg, qbeta, kg, kbeta);
    // 3) Fused attention
    attn_kernel<<<Bd * NHd * (Td / 64), 256, ATTN_SMEM>>>(qkv_p, rel, y_p);
    // 4) Output projection  (BM=64 -> 512 CTAs, grid-limit fix)
    {
        dim3 grid(Cd / 64, Md / 64);
        sgemm_bias_kernel<64><<<grid, 256>>>(y_p, w_proj, b_proj, out, Cd, Cd);
    }
}

// round 6
// speedup vs baseline: 1.0109x; 1.0109x over previous
#include <cuda_runtime.h>

#define Bd 8
#define Td 512
#define Cd 512
#define NHd 8
#define HDd 64
#define Md (Bd * Td)            // 4096
#define QKVN (3 * Cd)           // 1536

__device__ float g_qkv[Md * QKVN];
__device__ float g_y[Md * Cd];

__device__ __forceinline__ unsigned f2tf(float f) {
    unsigned u; asm("cvt.rna.tf32.f32 %0, %1;" : "=r"(u) : "f"(f)); return u;
}
__device__ __forceinline__ uint4 cvt4(float4 v) {
    return make_uint4(f2tf(v.x), f2tf(v.y), f2tf(v.z), f2tf(v.w));
}
__device__ __forceinline__ void mma_tf32(float c[4],
    unsigned a0, unsigned a1, unsigned a2, unsigned a3,
    unsigned b0, unsigned b1)
{
    asm volatile(
        "mma.sync.aligned.m16n8k8.row.col.f32.tf32.tf32.f32 "
        "{%0,%1,%2,%3}, {%4,%5,%6,%7}, {%8,%9}, {%0,%1,%2,%3};"
        : "+f"(c[0]), "+f"(c[1]), "+f"(c[2]), "+f"(c[3])
        : "r"(a0), "r"(a1), "r"(a2), "r"(a3), "r"(b0), "r"(b1));
}

// ---------------------------------------------------------------------------
// tf32 SGEMM (unchanged from R5)
// ---------------------------------------------------------------------------
#define GPITCH 36
template<int BM>
__global__ __launch_bounds__(256) void sgemm_bias_kernel(
    const float* __restrict__ A, const float* __restrict__ W,
    const float* __restrict__ bias, float* __restrict__ out,
    int Kdim, int Ndim)
{
    constexpr int MI = BM / 64;
    constexpr int AL = BM / 32;
    __shared__ unsigned As[BM * GPITCH];
    __shared__ unsigned Bs[64 * GPITCH];
    const int tid = threadIdx.x;
    const int lane = tid & 31, warp = tid >> 5;
    const int g = lane >> 2, tig = lane & 3;
    const int wm = (warp & 3) * (BM / 4);
    const int wn = (warp >> 2) << 5;
    const int m0 = blockIdx.y * BM, n0 = blockIdx.x << 6;

    const int lrow = tid >> 3;
    const int lk4 = (tid & 7) << 2;

    float c[MI][4][4] = {};
    float4 avr[AL], bvr[2];

    #pragma unroll
    for (int i = 0; i < AL; i++)
        avr[i] = *(const float4*)&A[(size_t)(m0 + lrow + (i << 5)) * Kdim + lk4];
    #pragma unroll
    for (int i = 0; i < 2; i++)
        bvr[i] = *(const float4*)&W[(size_t)(n0 + lrow + (i << 5)) * Kdim + lk4];

    for (int k0 = 0; k0 < Kdim; k0 += 32) {
        #pragma unroll
        for (int i = 0; i < AL; i++)
            *(uint4*)&As[(lrow + (i << 5)) * GPITCH + lk4] = cvt4(avr[i]);
        #pragma unroll
        for (int i = 0; i < 2; i++)
            *(uint4*)&Bs[(lrow + (i << 5)) * GPITCH + lk4] = cvt4(bvr[i]);
        __syncthreads();

        if (k0 + 32 < Kdim) {
            #pragma unroll
            for (int i = 0; i < AL; i++)
                avr[i] = *(const float4*)&A[(size_t)(m0 + lrow + (i << 5)) * Kdim + k0 + 32 + lk4];
            #pragma unroll
            for (int i = 0; i < 2; i++)
                bvr[i] = *(const float4*)&W[(size_t)(n0 + lrow + (i << 5)) * Kdim + k0 + 32 + lk4];
        }

        #pragma unroll
        for (int ks = 0; ks < 4; ks++) {
            const int ko = ks << 3;
            unsigned a[MI][4];
            #pragma unroll
            for (int i = 0; i < MI; i++) {
                int mb = wm + (i << 4);
                a[i][0] = As[(mb + g) * GPITCH + ko + tig];
                a[i][1] = As[(mb + g + 8) * GPITCH + ko + tig];
                a[i][2] = As[(mb + g) * GPITCH + ko + tig + 4];
                a[i][3] = As[(mb + g + 8) * GPITCH + ko + tig + 4];
            }
            unsigned b[4][2];
            #pragma unroll
            for (int j = 0; j < 4; j++) {
                int nb = wn + (j << 3);
                b[j][0] = Bs[(nb + g) * GPITCH + ko + tig];
                b[j][1] = Bs[(nb + g) * GPITCH + ko + tig + 4];
            }
            #pragma unroll
            for (int i = 0; i < MI; i++)
                #pragma unroll
                for (int j = 0; j < 4; j++)
                    mma_tf32(c[i][j], a[i][0], a[i][1], a[i][2], a[i][3],
                             b[j][0], b[j][1]);
        }
        __syncthreads();
    }

    #pragma unroll
    for (int i = 0; i < MI; i++) {
        #pragma unroll
        for (int j = 0; j < 4; j++) {
            int row = m0 + wm + (i << 4) + g;
            int col = n0 + wn + (j << 3) + (tig << 1);
            float b0 = bias[col], b1 = bias[col + 1];
            *(float2*)&out[(size_t)row * Ndim + col] =
                make_float2(c[i][j][0] + b0, c[i][j][1] + b1);
            *(float2*)&out[(size_t)(row + 8) * Ndim + col] =
                make_float2(c[i][j][2] + b0, c[i][j][3] + b1);
        }
    }
}

// ---------------------------------------------------------------------------
// LayerNorm q,k (unchanged)
// ---------------------------------------------------------------------------
__global__ __launch_bounds__(256) void ln_qk_kernel(
    float* __restrict__ qkv,
    const float* __restrict__ qg, const float* __restrict__ qb,
    const float* __restrict__ kg, const float* __restrict__ kb)
{
    const int bt = blockIdx.x;
    float* row = qkv + (size_t)bt * QKVN;
    const int tid = threadIdx.x;
    const int lane = tid & 31, w = tid >> 5;
    __shared__ float sh_s[8], sh_ss[8];

    #pragma unroll
    for (int seg = 0; seg < 2; seg++) {
        float* p = row + seg * Cd;
        const float* gam = seg ? kg : qg;
        const float* bet = seg ? kb : qb;
        float x0 = p[tid], x1 = p[tid + 256];
        float s = x0 + x1;
        float ss = x0 * x0 + x1 * x1;
        #pragma unroll
        for (int o = 16; o; o >>= 1) {
            s  += __shfl_xor_sync(0xffffffffu, s, o);
            ss += __shfl_xor_sync(0xffffffffu, ss, o);
        }
        if (lane == 0) { sh_s[w] = s; sh_ss[w] = ss; }
        __syncthreads();
        float tot = 0.f, tot2 = 0.f;
        #pragma unroll
        for (int i = 0; i < 8; i++) { tot += sh_s[i]; tot2 += sh_ss[i]; }
        float mu = tot * (1.0f / 512.0f);
        float var = tot2 * (1.0f / 512.0f) - mu * mu;
        float rstd = rsqrtf(var + 1e-5f);
        p[tid]       = (x0 - mu) * rstd * gam[tid]       + bet[tid];
        p[tid + 256] = (x1 - mu) * rstd * gam[tid + 256] + bet[tid + 256];
        __syncthreads();
    }
}

// ---------------------------------------------------------------------------
// Flash attention with per-tile rel bias. 2 CTAs/SM (102 KB smem).
// Per CTA: (b, h, 64-row q block). Online softmax; O accum in registers.
// ---------------------------------------------------------------------------
#define FP 68                    // pitch for 64-wide tiles
#define PCP 132                  // Pcat pitch (128 cols)
// smem (floats): q 64*FP | bufA 128*FP (rel -> V) | kst 64*FP (K -> S/P tile)
//                pcat 64*PCP | m 64 | l 64 | alpha 64
#define OFF_Q    0
#define OFF_BUFA (64 * FP)
#define OFF_KST  (OFF_BUFA + 128 * FP)
#define OFF_PCAT (OFF_KST + 64 * FP)
#define OFF_M    (OFF_PCAT + 64 * PCP)
#define OFF_L    (OFF_M + 64)
#define OFF_AL   (OFF_L + 64)
#define ATTN_SMEM ((OFF_AL + 64) * 4)    // 104960-ish bytes

__global__ __launch_bounds__(256) void attn_kernel(
    const float* __restrict__ qkv,
    const float* __restrict__ rel_emb,
    float* __restrict__ yout)
{
    const int blk = blockIdx.x;
    const int qb = 7 - (blk & 7);        // heavy blocks first
    const int h  = (blk >> 3) & 7;
    const int b  = blk >> 6;
    const int q0 = qb << 6;
    const int ntiles = qb + 1;

    extern __shared__ float sm[];
    unsigned* q_s  = (unsigned*)(sm + OFF_Q);
    unsigned* bufA = (unsigned*)(sm + OFF_BUFA);   // rel tiles, then V [d][key]
    unsigned* kst_u = (unsigned*)(sm + OFF_KST);   // K tile, then P (tf32)
    float*    s_t  = sm + OFF_KST;                 // S tile (fp32 view)
    float*    pcat = sm + OFF_PCAT;
    float*    m_s  = sm + OFF_M;
    float*    l_s  = sm + OFF_L;
    float*    al_s = sm + OFF_AL;

    const int tid = threadIdx.x;
    const int lane = tid & 31, warp = tid >> 5;
    const int g = lane >> 2, tig = lane & 3;
    const int qm = (warp & 3) << 4;      // warp q rows
    const int wn = (warp >> 2) << 5;     // warp n cols

    const int lr = tid >> 4;             // 0..15
    const int lc4 = (tid & 15) << 2;     // 0..60

    // ---- load q block (row-major tf32); init stats ----
    {
        const float* qbase = qkv + (size_t)(b * Td + q0) * QKVN + h * HDd;
        #pragma unroll
        for (int i = 0; i < 4; i++) {
            int r = lr + (i << 4);
            float4 v = *(const float4*)&qbase[(size_t)r * QKVN + lc4];
            *(uint4*)&q_s[r * FP + lc4] = cvt4(v);
        }
    }
    if (tid < 64) { m_s[tid] = -1e30f; l_s[tid] = 0.f; }

    float o[4][4] = {};
    const float scale = 0.125f;

    for (int kt = 0; kt < ntiles; kt++) {
        const int D = q0 - (kt << 6);    // multiple of 64; 0 only on diagonal
        const bool haveLo = (D != 0);

        // ---- load K tile [key][d] and rel band into bufA rows 0..127 ----
        {
            const float* kbase = qkv + (size_t)(b * Td + (kt << 6)) * QKVN + Cd + h * HDd;
            #pragma unroll
            for (int i = 0; i < 4; i++) {
                int r = lr + (i << 4);
                float4 v = *(const float4*)&kbase[(size_t)r * QKVN + lc4];
                *(uint4*)&kst_u[r * FP + lc4] = cvt4(v);
            }
            #pragma unroll
            for (int i = 0; i < 8; i++) {
                int rr = lr + (i << 4);          // bufA row 0..127
                int delta = D - 64 + rr;
                if (delta >= 0) {
                    float4 v = *(const float4*)&rel_emb[(size_t)delta * Cd + h * HDd + lc4];
                    *(uint4*)&bufA[rr * FP + lc4] = cvt4(v);
                }
            }
        }
        __syncthreads();   // (a)

        // ---- MMA: S = q@K^T ; P = q@rel^T (2 n-tiles) ----
        float cS[4][4] = {};
        float cP[2][4][4] = {};
        #pragma unroll
        for (int ks = 0; ks < 8; ks++) {
            const int ko = ks << 3;
            unsigned a0 = q_s[(qm + g) * FP + ko + tig];
            unsigned a1 = q_s[(qm + g + 8) * FP + ko + tig];
            unsigned a2 = q_s[(qm + g) * FP + ko + tig + 4];
            unsigned a3 = q_s[(qm + g + 8) * FP + ko + tig + 4];
            #pragma unroll
            for (int j = 0; j < 4; j++) {
                int nb = wn + (j << 3) + g;
                unsigned b0 = kst_u[nb * FP + ko + tig];
                unsigned b1 = kst_u[nb * FP + ko + tig + 4];
                mma_tf32(cS[j], a0, a1, a2, a3, b0, b1);
                unsigned h0 = bufA[(64 + nb) * FP + ko + tig];
                unsigned h1 = bufA[(64 + nb) * FP + ko + tig + 4];
                mma_tf32(cP[1][j], a0, a1, a2, a3, h0, h1);
                if (haveLo) {
                    unsigned l0 = bufA[nb * FP + ko + tig];
                    unsigned l1 = bufA[nb * FP + ko + tig + 4];
                    mma_tf32(cP[0][j], a0, a1, a2, a3, l0, l1);
                }
            }
        }
        // write Pcat
        #pragma unroll
        for (int t = 0; t < 2; t++) {
            if (t == 0 && !haveLo) continue;
            #pragma unroll
            for (int j = 0; j < 4; j++) {
                int col = (t << 6) + wn + (j << 3) + (tig << 1);
                *(float2*)&pcat[(qm + g) * PCP + col] =
                    make_float2(cP[t][j][0], cP[t][j][1]);
                *(float2*)&pcat[(qm + g + 8) * PCP + col] =
                    make_float2(cP[t][j][2], cP[t][j][3]);
            }
        }
        __syncthreads();   // (d): kst & rel reads done; pcat visible

        // ---- write S + bias (scaled, masked) into s_t; load V into bufA ----
        #pragma unroll
        for (int j = 0; j < 4; j++) {
            int ck = wn + (j << 3) + (tig << 1);
            int r0 = qm + g, r1 = qm + g + 8;
            #pragma unroll
            for (int u = 0; u < 2; u++) {
                int c = ck + u;
                float v0 = (r0 - c + D >= 0)
                    ? (cS[j][u] + pcat[r0 * PCP + 64 + r0 - c]) * scale : -1e30f;
                float v1 = (r1 - c + D >= 0)
                    ? (cS[j][2 + u] + pcat[r1 * PCP + 64 + r1 - c]) * scale : -1e30f;
                s_t[r0 * FP + c] = v0;
                s_t[r1 * FP + c] = v1;
            }
        }
        {
            const float* vbase = qkv + (size_t)(b * Td + (kt << 6)) * QKVN + 2 * Cd + h * HDd;
            #pragma unroll
            for (int i = 0; i < 4; i++) {
                int key = lr + (i << 4);
                float4 v = *(const float4*)&vbase[(size_t)key * QKVN + lc4];
                bufA[(lc4 + 0) * FP + key] = f2tf(v.x);
                bufA[(lc4 + 1) * FP + key] = f2tf(v.y);
                bufA[(lc4 + 2) * FP + key] = f2tf(v.z);
                bufA[(lc4 + 3) * FP + key] = f2tf(v.w);
            }
        }
        __syncthreads();   // (f)

        // ---- online softmax update (warp w owns rows w*8..w*8+7) ----
        #pragma unroll
        for (int rr = 0; rr < 8; rr++) {
            int r = (warp << 3) + rr;
            float v1 = s_t[r * FP + lane];
            float v2 = s_t[r * FP + lane + 32];
            float tmax = fmaxf(v1, v2);
            #pragma unroll
            for (int oo = 16; oo; oo >>= 1)
                tmax = fmaxf(tmax, __shfl_xor_sync(0xffffffffu, tmax, oo));
            float m_old = m_s[r];
            float m_new = fmaxf(m_old, tmax);
            float p1 = __expf(v1 - m_new);
            float p2 = __expf(v2 - m_new);
            float tsum = p1 + p2;
            #pragma unroll
            for (int oo = 16; oo; oo >>= 1)
                tsum += __shfl_xor_sync(0xffffffffu, tsum, oo);
            float alpha = __expf(m_old - m_new);
            if (lane == 0) {
                l_s[r] = l_s[r] * alpha + tsum;
                m_s[r] = m_new;
                al_s[r] = alpha;
            }
            kst_u[r * FP + lane]      = f2tf(p1);
            kst_u[r * FP + lane + 32] = f2tf(p2);
        }
        __syncthreads();   // (h)

        // ---- rescale O, accumulate O += P @ V ----
        {
            float a0 = al_s[qm + g];
            float a1 = al_s[qm + g + 8];
            #pragma unroll
            for (int j = 0; j < 4; j++) {
                o[j][0] *= a0; o[j][1] *= a0;
                o[j][2] *= a1; o[j][3] *= a1;
            }
        }
        #pragma unroll
        for (int ks = 0; ks < 8; ks++) {
            const int kl = ks << 3;
            unsigned a0 = kst_u[(qm + g) * FP + kl + tig];
            unsigned a1 = kst_u[(qm + g + 8) * FP + kl + tig];
            unsigned a2 = kst_u[(qm + g) * FP + kl + tig + 4];
            unsigned a3 = kst_u[(qm + g + 8) * FP + kl + tig + 4];
            #pragma unroll
            for (int j = 0; j < 4; j++) {
                int nb = wn + (j << 3) + g;
                unsigned b0 = bufA[nb * FP + kl + tig];
                unsigned b1 = bufA[nb * FP + kl + tig + 4];
                mma_tf32(o[j], a0, a1, a2, a3, b0, b1);
            }
        }
        __syncthreads();   // (j)
    }

    // ---- finalize: O /= l, store ----
    {
        float inv0 = 1.0f / l_s[qm + g];
        float inv1 = 1.0f / l_s[qm + g + 8];
        int row0 = b * Td + q0 + qm + g;
        #pragma unroll
        for (int j = 0; j < 4; j++) {
            int col = h * HDd + wn + (j << 3) + (tig << 1);
            *(float2*)&yout[(size_t)row0 * Cd + col] =
                make_float2(o[j][0] * inv0, o[j][1] * inv0);
            *(float2*)&yout[(size_t)(row0 + 8) * Cd + col] =
                make_float2(o[j][2] * inv1, o[j][3] * inv1);
        }
    }
}

// ---------------------------------------------------------------------------
extern "C" void kernel_launch(void* const* d_in, const int* in_sizes, int n_in,
                              void* d_out, int out_size)
{
    const float* x      = (const float*)d_in[0];
    const float* w_attn = (const float*)d_in[1];
    const float* b_attn = (const float*)d_in[2];
    const float* w_proj = (const float*)d_in[3];
    const float* b_proj = (const float*)d_in[4];
    const float* qg     = (const float*)d_in[5];
    const float* qbeta  = (const float*)d_in[6];
    const float* kg     = (const float*)d_in[7];
    const float* kbeta  = (const float*)d_in[8];
    const float* rel    = (const float*)d_in[9];
    float* out = (float*)d_out;

    float *qkv_p, *y_p;
    cudaGetSymbolAddress((void**)&qkv_p, g_qkv);
    cudaGetSymbolAddress((void**)&y_p, g_y);

    cudaFuncSetAttribute(attn_kernel,
                         cudaFuncAttributeMaxDynamicSharedMemorySize, ATTN_SMEM);

    // 1) QKV projection
    {
        dim3 grid(QKVN / 64, Md / 128);
        sgemm_bias_kernel<128><<<grid, 256>>>(x, w_attn, b_attn, qkv_p, Cd, QKVN);
    }
    // 2) LayerNorm q,k in place
    ln_qk_kernel<<<Md, 256>>>(qkv_p, qg, qbeta, kg, kbeta);
    // 3) Flash attention
    attn_kernel<<<Bd * NHd * (Td / 64), 256, ATTN_SMEM>>>(qkv_p, rel, y_p);
    // 4) Output projection
    {
        dim3 grid(Cd / 64, Md / 64);
        sgemm_bias_kernel<64><<<grid, 256>>>(y_p, w_proj, b_proj, out, Cd, Cd);
    }
}